// round 4
// baseline (speedup 1.0000x reference)
#include <cuda_runtime.h>
#include <math.h>

#define D      256
#define SEQ    2046
#define HEADS  8
#define DK     32
#define MHALF  1024
#define NGROUP 64   // B(4) * rate(2) * heads(8)
#define QT     64   // queries (= threads) per attention CTA
#define KT     128  // keys per smem tile

// group-major qkv scratch: [ (b*2+r)*8+h ][ i (0..1023) ][ d (0..31) ]
__device__ float g_qkv[(size_t)NGROUP * MHALF * DK];

typedef unsigned long long u64;

__device__ __forceinline__ u64 pack2(float x, float y) {
    u64 r; asm("mov.b64 %0, {%1, %2};" : "=l"(r) : "f"(x), "f"(y)); return r;
}
__device__ __forceinline__ float2 unpack2(u64 v) {
    float2 f; asm("mov.b64 {%0, %1}, %2;" : "=f"(f.x), "=f"(f.y) : "l"(v)); return f;
}
__device__ __forceinline__ u64 ffma2(u64 a, u64 b, u64 c) {
    u64 d; asm("fma.rn.f32x2 %0, %1, %2, %3;" : "=l"(d) : "l"(a), "l"(b), "l"(c)); return d;
}
__device__ __forceinline__ u64 fmul2(u64 a, u64 b) {
    u64 d; asm("mul.rn.f32x2 %0, %1, %2;" : "=l"(d) : "l"(a), "l"(b)); return d;
}
__device__ __forceinline__ float ex2a(float x) {
    float y; asm("ex2.approx.f32 %0, %1;" : "=f"(y) : "f"(x)); return y;
}

// load 32 floats (16 f32x2 words) from a 16B-aligned pointer
__device__ __forceinline__ void load16(u64* dst, const void* p) {
    const ulonglong2* s = (const ulonglong2*)p;
#pragma unroll
    for (int v = 0; v < 8; v++) { ulonglong2 u = s[v]; dst[2 * v] = u.x; dst[2 * v + 1] = u.y; }
}

// packed dot product of two 32-float vectors held as 16 f32x2 words
__device__ __forceinline__ float dot16(const u64* a, const u64* b) {
    u64 s0 = fmul2(a[0], b[0]);
    u64 s1 = fmul2(a[1], b[1]);
#pragma unroll
    for (int v = 2; v < 16; v += 2) {
        s0 = ffma2(a[v], b[v], s0);
        s1 = ffma2(a[v + 1], b[v + 1], s1);
    }
    float2 f0 = unpack2(s0), f1 = unpack2(s1);
    return (f0.x + f0.y) + (f1.x + f1.y);
}

// ---------------------------------------------------------------------------
// Kernel 1: qkv = pad(x) @ W + b, written into group-major layout.
// ---------------------------------------------------------------------------
__global__ void __launch_bounds__(256) qkv_gemm_kernel(const float* __restrict__ x,
                                                       const float* __restrict__ W,
                                                       const float* __restrict__ bias) {
    __shared__ float As[16][68];
    __shared__ float Bs[16][64];

    const int tid  = threadIdx.x;
    const int ty   = tid >> 4;
    const int tx   = tid & 15;
    const int row0 = blockIdx.x * 64;
    const int col0 = blockIdx.y * 64;

    float acc[4][4];
#pragma unroll
    for (int i = 0; i < 4; i++)
#pragma unroll
        for (int j = 0; j < 4; j++) acc[i][j] = 0.f;

    const int ar = tid >> 2;
    const int ak = (tid & 3) << 2;
    const int grow = row0 + ar;
    const int gb = grow >> 11;
    const int gs = grow & 2047;
    const float* xrow = (gs < SEQ) ? (x + ((size_t)gb * SEQ + gs) * D) : nullptr;

    const int bk  = tid >> 4;
    const int bn4 = (tid & 15) << 2;

    for (int k0 = 0; k0 < D; k0 += 16) {
        float4 av = make_float4(0.f, 0.f, 0.f, 0.f);
        if (xrow) av = *(const float4*)(xrow + k0 + ak);
        As[ak + 0][ar] = av.x;
        As[ak + 1][ar] = av.y;
        As[ak + 2][ar] = av.z;
        As[ak + 3][ar] = av.w;

        *(float4*)&Bs[bk][bn4] = *(const float4*)&W[(size_t)(k0 + bk) * D + col0 + bn4];
        __syncthreads();

#pragma unroll
        for (int k = 0; k < 16; k++) {
            float4 a4 = *(const float4*)&As[k][ty << 2];
            float4 b4 = *(const float4*)&Bs[k][tx << 2];
            acc[0][0] += a4.x * b4.x; acc[0][1] += a4.x * b4.y; acc[0][2] += a4.x * b4.z; acc[0][3] += a4.x * b4.w;
            acc[1][0] += a4.y * b4.x; acc[1][1] += a4.y * b4.y; acc[1][2] += a4.y * b4.z; acc[1][3] += a4.y * b4.w;
            acc[2][0] += a4.z * b4.x; acc[2][1] += a4.z * b4.y; acc[2][2] += a4.z * b4.z; acc[2][3] += a4.z * b4.w;
            acc[3][0] += a4.w * b4.x; acc[3][1] += a4.w * b4.y; acc[3][2] += a4.w * b4.z; acc[3][3] += a4.w * b4.w;
        }
        __syncthreads();
    }

#pragma unroll
    for (int i = 0; i < 4; i++) {
        const int grow2 = row0 + (ty << 2) + i;
        const int b = grow2 >> 11;
        const int s = grow2 & 2047;
        const int ii = s >> 1;
        const int r  = s & 1;
#pragma unroll
        for (int j = 0; j < 4; j++) {
            const int c = col0 + (tx << 2) + j;
            const int h = c >> 5;
            const int d = c & 31;
            g_qkv[((size_t)((b * 2 + r) * HEADS + h) * MHALF + ii) * DK + d] = acc[i][j] + bias[c];
        }
    }
}

// ---------------------------------------------------------------------------
// Kernel 2: per-group flash attention with packed f32x2 math.
// Logits kept in base-2 units (scale folded with log2e), ex2.approx for exp.
// ---------------------------------------------------------------------------
__global__ void __launch_bounds__(QT) attn_kernel(float* __restrict__ out) {
    const int g = blockIdx.y;                 // 0..63
    const int t = threadIdx.x;                // 0..63
    const int i = blockIdx.x * QT + t;        // query row in group

    const float* Xg = g_qkv + (size_t)g * MHALF * DK;
    const float* qp = Xg + (size_t)i * DK;

    // 1/sqrt(32) * log2(e): logits live in base-2 from the start
    const float SCALE2 = 0.17677669529663687f * 1.4426950408889634f;

    u64 q[16];
    load16(q, qp);

    // ---- prologue: local trio (i-1, i, i+1 in decimated index) ----
    float l1 = dot16(q, q) * SCALE2;
    float l0 = 0.f, l2 = 0.f;
    if (i > 0) {
        u64 km[16]; load16(km, qp - DK);
        l0 = dot16(q, km) * SCALE2;
    }
    if (i < MHALF - 1) {
        u64 kp[16]; load16(kp, qp + DK);
        l2 = dot16(q, kp) * SCALE2;
    }

    float mx = fmaxf(l1, fmaxf(l0, l2));
    const float e0 = ex2a(l0 - mx);
    const float e1 = ex2a(l1 - mx);
    const float e2 = ex2a(l2 - mx);
    float denom = e0 + e1 + e2;

    u64 acc[16];
    {
        const u64 e1p = pack2(e1, e1);
#pragma unroll
        for (int v = 0; v < 16; v++) acc[v] = fmul2(q[v], e1p);
    }
    if (i > 0) {
        u64 km[16]; load16(km, qp - DK);
        const u64 e0p = pack2(e0, e0);
#pragma unroll
        for (int v = 0; v < 16; v++) acc[v] = ffma2(km[v], e0p, acc[v]);
    }
    if (i < MHALF - 1) {
        u64 kp[16]; load16(kp, qp + DK);
        const u64 e2p = pack2(e2, e2);
#pragma unroll
        for (int v = 0; v < 16; v++) acc[v] = ffma2(kp[v], e2p, acc[v]);
    }

    // pre-scale q: from here on q is only used for dot products
    {
        const u64 sc = pack2(SCALE2, SCALE2);
#pragma unroll
        for (int v = 0; v < 16; v++) q[v] = fmul2(q[v], sc);
    }

    // ---- main pass over all 1024 keys, online softmax ----
    __shared__ float ks[KT * DK];
    for (int kt = 0; kt < MHALF / KT; kt++) {
        __syncthreads();
        const float4* src = (const float4*)(Xg + (size_t)kt * KT * DK);
        float4* dst = (float4*)ks;
#pragma unroll
        for (int v = 0; v < (KT * DK / 4) / QT; v++) dst[t + QT * v] = src[t + QT * v];
        __syncthreads();

        for (int j = 0; j < KT; j++) {
            u64 kr[16];
            load16(kr, ks + j * DK);

            // base-2 logit: q already carries SCALE2
            u64 s0 = fmul2(q[0], kr[0]);
            u64 s1 = fmul2(q[1], kr[1]);
#pragma unroll
            for (int v = 2; v < 16; v += 2) {
                s0 = ffma2(q[v], kr[v], s0);
                s1 = ffma2(q[v + 1], kr[v + 1], s1);
            }
            float2 f0 = unpack2(s0), f1 = unpack2(s1);
            const float s = (f0.x + f0.y) + (f1.x + f1.y);

            if (s > mx) {   // rare: diagonal logit dominates, almost never taken
                const float fct = ex2a(mx - s);
                denom *= fct;
                const u64 fp = pack2(fct, fct);
#pragma unroll
                for (int v = 0; v < 16; v++) acc[v] = fmul2(acc[v], fp);
                mx = s;
            }
            const float w = ex2a(s - mx);
            denom += w;
            const u64 wp = pack2(w, w);
#pragma unroll
            for (int v = 0; v < 16; v++) acc[v] = ffma2(kr[v], wp, acc[v]);
        }
    }

    // ---- write back (skip padded rows s >= 2046) ----
    const int h = g & 7;
    const int r = (g >> 3) & 1;
    const int b = g >> 4;
    const int s = 2 * i + r;
    if (s < SEQ) {
        const float inv = 1.f / denom;
        const u64 ip = pack2(inv, inv);
        ulonglong2* op = (ulonglong2*)(out + ((size_t)b * SEQ + s) * D + h * DK);
#pragma unroll
        for (int v = 0; v < 8; v++) {
            ulonglong2 w2;
            w2.x = fmul2(acc[2 * v], ip);
            w2.y = fmul2(acc[2 * v + 1], ip);
            op[v] = w2;
        }
    }
}

extern "C" void kernel_launch(void* const* d_in, const int* in_sizes, int n_in,
                              void* d_out, int out_size) {
    const float* x = (const float*)d_in[0];
    const float* W = (const float*)d_in[1];
    const float* b = (const float*)d_in[2];
    float* out = (float*)d_out;

    dim3 gemm_grid(8192 / 64, D / 64);   // 128 x 4
    qkv_gemm_kernel<<<gemm_grid, 256>>>(x, W, b);

    dim3 attn_grid(MHALF / QT, NGROUP);  // 16 x 64
    attn_kernel<<<attn_grid, QT>>>(out);
}